// round 6
// baseline (speedup 1.0000x reference)
#include <cuda_runtime.h>
#include <cuda_bf16.h>
#include <math.h>
#include <stdint.h>

#define Q_LEN 2048
#define K_LEN 2048
#define BATCH 4
#define HEADS 8
#define EMB 512
#define INP 544
#define HD 32
#define BHN (BATCH*HEADS)

#define TQ 128
#define TK 128
#define NT (K_LEN/TK)
#define LDK 40          // bf16 pitch for q/k tiles (80 B rows)
#define LDS_ 132        // f32 pitch for stage (528 B rows -> conflict-free)

// projected q/k, bf16 hi/lo split, layout [bh][seq][32]
__device__ __nv_bfloat16 g_qh[(size_t)BHN * Q_LEN * HD];
__device__ __nv_bfloat16 g_ql[(size_t)BHN * Q_LEN * HD];
__device__ __nv_bfloat16 g_kh[(size_t)BHN * K_LEN * HD];
__device__ __nv_bfloat16 g_kl[(size_t)BHN * K_LEN * HD];
__device__ float g_pe[(size_t)Q_LEN * EMB];

// ───────────────────────── PE table ─────────────────────────
__global__ void pe_kernel() {
    int idx = blockIdx.x * 256 + threadIdx.x;
    int pos = idx >> 8;
    int i2  = idx & 255;
    float e = 2.0f * (float)i2;
    float div = expf(e * (-9.210340371976184f / 512.0f));
    float a = (float)pos * div;
    g_pe[(size_t)pos * EMB + 2 * i2]     = sinf(a);
    g_pe[(size_t)pos * EMB + 2 * i2 + 1] = cosf(a);
}

// ───────────────────────── projection ─────────────────────────
__global__ void __launch_bounds__(256, 2) proj_kernel(
        const float* __restrict__ qin, const float* __restrict__ kin,
        const float* __restrict__ Wq,  const float* __restrict__ bq,
        const float* __restrict__ Wk,  const float* __restrict__ bk) {
    __shared__ float As[32 * 36];
    __shared__ float Bs[32 * 256];

    const int is_q = (blockIdx.z == 0);
    const float* in   = is_q ? qin : kin;
    const float* W    = is_q ? Wq  : Wk;
    const float* bias = is_q ? bq  : bk;
    const int off     = is_q ? 0 : 256;
    __nv_bfloat16* oh = is_q ? g_qh : g_kh;
    __nv_bfloat16* ol = is_q ? g_ql : g_kl;

    int b  = blockIdx.y;
    int q0 = blockIdx.x * 32;
    int col = threadIdx.x;

    float acc[32];
    float bv = bias[off + col];
#pragma unroll
    for (int r = 0; r < 32; r++) acc[r] = bv;

    for (int et = 0; et < 16; et++) {
        {
            int i = threadIdx.x;
#pragma unroll
            for (int j = 0; j < 4; j++, i += 256) {
                int r = i >> 5, e = i & 31;
                int ge = et * 32 + e;
                float v = in[((size_t)(q0 + r) * BATCH + b) * EMB + ge];
                if (is_q) v += g_pe[(size_t)(q0 + r) * EMB + ge];
                As[r * 36 + e] = v;
            }
        }
#pragma unroll
        for (int e = 0; e < 32; e++)
            Bs[e * 256 + col] = W[(size_t)(et * 32 + e) * INP + off + col];
        __syncthreads();

#pragma unroll
        for (int e4 = 0; e4 < 8; e4++) {
            float b0 = Bs[(e4 * 4 + 0) * 256 + col];
            float b1 = Bs[(e4 * 4 + 1) * 256 + col];
            float b2 = Bs[(e4 * 4 + 2) * 256 + col];
            float b3 = Bs[(e4 * 4 + 3) * 256 + col];
#pragma unroll
            for (int r = 0; r < 32; r++) {
                float4 a4 = *(const float4*)&As[r * 36 + e4 * 4];
                acc[r] += a4.x * b0;
                acc[r] += a4.y * b1;
                acc[r] += a4.z * b2;
                acc[r] += a4.w * b3;
            }
        }
        __syncthreads();
    }

    int h = col >> 5, d = col & 31;
#pragma unroll
    for (int r = 0; r < 32; r++) {
        float v = acc[r];
        __nv_bfloat16 hi = __float2bfloat16(v);
        __nv_bfloat16 lo = __float2bfloat16(v - __bfloat162float(hi));
        size_t idx = ((size_t)(b * HEADS + h) * Q_LEN + (q0 + r)) * HD + d;
        oh[idx] = hi;
        ol[idx] = lo;
    }
}

// ───────────────────────── attention (HMMA + staged epilogue) ─────────────────────────
__device__ __forceinline__ void mma_bf16(float& d0, float& d1, float& d2, float& d3,
                                         const uint32_t a[4], const uint32_t b[2]) {
    asm volatile(
        "mma.sync.aligned.m16n8k16.row.col.f32.bf16.bf16.f32 "
        "{%0,%1,%2,%3}, {%4,%5,%6,%7}, {%8,%9}, {%0,%1,%2,%3};\n"
        : "+f"(d0), "+f"(d1), "+f"(d2), "+f"(d3)
        : "r"(a[0]), "r"(a[1]), "r"(a[2]), "r"(a[3]), "r"(b[0]), "r"(b[1]));
}

// smem layout (bytes)
#define OFF_QH   0          // 10240
#define OFF_QL   10240      // 10240
#define OFF_K    20480      // KH 10240 + KL 10240
#define OFF_ST   40960      // 128*132*4 = 67584
#define OFF_RINV 108544     // 512
#define OFF_KPM  109056     // 2048
#define SMEM_ATTN 111104

__global__ void __launch_bounds__(256, 2) attn_kernel(
        const unsigned char* __restrict__ am,
        const unsigned char* __restrict__ kpm,
        float* __restrict__ out) {
    extern __shared__ char smem[];
    __nv_bfloat16* qh_s = (__nv_bfloat16*)(smem + OFF_QH);
    __nv_bfloat16* ql_s = (__nv_bfloat16*)(smem + OFF_QL);
    __nv_bfloat16* kh_s = (__nv_bfloat16*)(smem + OFF_K);
    __nv_bfloat16* kl_s = kh_s + 5120;
    float* stage  = (float*)(smem + OFF_ST);
    float* rinv_s = (float*)(smem + OFF_RINV);
    unsigned char* kpm_s = (unsigned char*)(smem + OFF_KPM);

    int tid = threadIdx.x, w = tid >> 5, lane = tid & 31;
    int g = lane >> 2, qr = lane & 3;
    int R0 = w * 16;
    int bh = blockIdx.y, b = bh >> 3, h = bh & 7;
    int q0 = blockIdx.x * TQ;

    // q tiles hi/lo
#pragma unroll
    for (int j = 0; j < 2; j++) {
        int i = tid + j * 256;
        int r = i >> 2, c = i & 3;
        size_t gi = ((size_t)bh * Q_LEN + q0 + r) * 4 + c;
        *(uint4*)(qh_s + r * LDK + c * 8) = ((const uint4*)g_qh)[gi];
        *(uint4*)(ql_s + r * LDK + c * 8) = ((const uint4*)g_ql)[gi];
    }
    if (tid < 128)
        ((uint4*)kpm_s)[tid] = ((const uint4*)(kpm + (size_t)b * K_LEN))[tid];
    // K tile 0
#pragma unroll
    for (int j = 0; j < 2; j++) {
        int i = tid + j * 256;
        int r = i >> 2, c = i & 3;
        size_t gi = ((size_t)bh * K_LEN + r) * 4 + c;
        *(uint4*)(kh_s + r * LDK + c * 8) = ((const uint4*)g_kh)[gi];
        *(uint4*)(kl_s + r * LDK + c * 8) = ((const uint4*)g_kl)[gi];
    }
    __syncthreads();

    // A fragments (whole kernel)
    uint32_t aH[2][4], aL[2][4];
#pragma unroll
    for (int kc = 0; kc < 2; kc++) {
        int c0 = kc * 16 + qr * 2;
        aH[kc][0] = *(const uint32_t*)(qh_s + (R0 + g    ) * LDK + c0);
        aH[kc][1] = *(const uint32_t*)(qh_s + (R0 + g + 8) * LDK + c0);
        aH[kc][2] = *(const uint32_t*)(qh_s + (R0 + g    ) * LDK + c0 + 8);
        aH[kc][3] = *(const uint32_t*)(qh_s + (R0 + g + 8) * LDK + c0 + 8);
        aL[kc][0] = *(const uint32_t*)(ql_s + (R0 + g    ) * LDK + c0);
        aL[kc][1] = *(const uint32_t*)(ql_s + (R0 + g + 8) * LDK + c0);
        aL[kc][2] = *(const uint32_t*)(ql_s + (R0 + g    ) * LDK + c0 + 8);
        aL[kc][3] = *(const uint32_t*)(ql_s + (R0 + g + 8) * LDK + c0 + 8);
    }
    int r1 = R0 + g, r2 = r1 + 8;

    float psum[16];
#pragma unroll
    for (int rr = 0; rr < 16; rr++) psum[rr] = 0.f;

    for (int u = 0; u < 2 * NT; u++) {
        int t = u & (NT - 1);
        int sweep = u >> 4;

        // MMA + stage
#pragma unroll 2
        for (int nt = 0; nt < 16; nt++) {
            int n0 = nt * 8;
            uint32_t bH[2][2], bL[2][2];
#pragma unroll
            for (int kc = 0; kc < 2; kc++) {
                int c0 = kc * 16 + qr * 2;
                bH[kc][0] = *(const uint32_t*)(kh_s + (n0 + g) * LDK + c0);
                bH[kc][1] = *(const uint32_t*)(kh_s + (n0 + g) * LDK + c0 + 8);
                bL[kc][0] = *(const uint32_t*)(kl_s + (n0 + g) * LDK + c0);
                bL[kc][1] = *(const uint32_t*)(kl_s + (n0 + g) * LDK + c0 + 8);
            }
            float d0 = 0.f, d1 = 0.f, d2 = 0.f, d3 = 0.f;
#pragma unroll
            for (int kc = 0; kc < 2; kc++) {
                mma_bf16(d0, d1, d2, d3, aH[kc], bH[kc]);
                mma_bf16(d0, d1, d2, d3, aH[kc], bL[kc]);
                mma_bf16(d0, d1, d2, d3, aL[kc], bH[kc]);
            }
            *(float2*)&stage[r1 * LDS_ + n0 + qr * 2] = make_float2(d0, d1);
            *(float2*)&stage[r2 * LDS_ + n0 + qr * 2] = make_float2(d2, d3);
        }
        __syncthreads();   // stage ready; K consumed

        // issue next K tile load (overlaps readout)
        if (u + 1 < 2 * NT) {
            int tt = (u + 1) & (NT - 1);
#pragma unroll
            for (int j = 0; j < 2; j++) {
                int i = tid + j * 256;
                int r = i >> 2, c = i & 3;
                size_t gi = ((size_t)bh * K_LEN + tt * TK + r) * 4 + c;
                *(uint4*)(kh_s + r * LDK + c * 8) = ((const uint4*)g_kh)[gi];
                *(uint4*)(kl_s + r * LDK + c * 8) = ((const uint4*)g_kl)[gi];
            }
        }

        // cooperative readout: warp w owns rows w*16..+15, lane owns 4 consecutive cols
        int kg = t * TK + lane * 4;
        const uchar4 p4 = *(const uchar4*)(kpm_s + kg);
        if (sweep == 0) {
#pragma unroll
            for (int rr = 0; rr < 16; rr++) {
                int row = R0 + rr;
                float4 v = *(const float4*)&stage[row * LDS_ + lane * 4];
                uchar4 m4 = *(const uchar4*)(am + (size_t)(q0 + row) * K_LEN + kg);
                float e0 = (m4.x | p4.x) ? 0.f : __expf(v.x);
                float e1 = (m4.y | p4.y) ? 0.f : __expf(v.y);
                float e2 = (m4.z | p4.z) ? 0.f : __expf(v.z);
                float e3 = (m4.w | p4.w) ? 0.f : __expf(v.w);
                psum[rr] += (e0 + e1) + (e2 + e3);
            }
            if (t == NT - 1) {
                // reduce rowsums -> rinv
#pragma unroll
                for (int rr = 0; rr < 16; rr++) {
                    float s = psum[rr];
#pragma unroll
                    for (int o = 16; o > 0; o >>= 1)
                        s += __shfl_xor_sync(0xffffffffu, s, o);
                    if (lane == 0) rinv_s[R0 + rr] = 1.0f / s;
                }
            }
        } else {
#pragma unroll
            for (int rr = 0; rr < 16; rr++) {
                int row = R0 + rr;
                float4 v = *(const float4*)&stage[row * LDS_ + lane * 4];
                uchar4 m4 = *(const uchar4*)(am + (size_t)(q0 + row) * K_LEN + kg);
                float iv = rinv_s[row];
                float e0 = (m4.x | p4.x) ? 0.f : __expf(v.x) * iv;
                float e1 = (m4.y | p4.y) ? 0.f : __expf(v.y) * iv;
                float e2 = (m4.z | p4.z) ? 0.f : __expf(v.z) * iv;
                float e3 = (m4.w | p4.w) ? 0.f : __expf(v.w) * iv;
                *(float4*)(out + (((size_t)(h * BATCH + b)) * Q_LEN + q0 + row) * K_LEN + kg)
                    = make_float4(e0, e1, e2, e3);
            }
        }
        __syncthreads();   // readout done + next K visible
    }
}

extern "C" void kernel_launch(void* const* d_in, const int* in_sizes, int n_in,
                              void* d_out, int out_size) {
    const float* query = (const float*)d_in[0];
    const float* key   = (const float*)d_in[1];
    const float* Wq    = (const float*)d_in[2];
    const float* bq    = (const float*)d_in[3];
    const float* Wk    = (const float*)d_in[4];
    const float* bk    = (const float*)d_in[5];
    const unsigned char* kpm = (const unsigned char*)d_in[6];
    const unsigned char* amk = (const unsigned char*)d_in[7];
    float* out = (float*)d_out;

    cudaFuncSetAttribute(attn_kernel, cudaFuncAttributeMaxDynamicSharedMemorySize, SMEM_ATTN);

    pe_kernel<<<2048, 256>>>();
    proj_kernel<<<dim3(Q_LEN / 32, BATCH, 2), 256>>>(query, key, Wq, bq, Wk, bk);
    attn_kernel<<<dim3(Q_LEN / TQ, BHN), 256, SMEM_ATTN>>>(amk, kpm, out);
}

// round 7
// speedup vs baseline: 1.1305x; 1.1305x over previous
#include <cuda_runtime.h>
#include <math.h>
#include <stdint.h>

#define Q_LEN 2048
#define K_LEN 2048
#define BATCH 4
#define HEADS 8
#define EMB 512
#define INP 544
#define HD 32
#define BHN (BATCH*HEADS)

// packed f32x2 helpers (Blackwell FFMA2 path)
#define FMA2(acc, a, b) \
    asm("fma.rn.f32x2 %0, %1, %2, %0;" : "+l"(acc) : "l"(a), "l"(b))
__device__ __forceinline__ uint64_t pack2(float lo, float hi) {
    uint64_t r;
    asm("mov.b64 %0, {%1, %2};" : "=l"(r) : "f"(lo), "f"(hi));
    return r;
}
__device__ __forceinline__ void unpack2(float& lo, float& hi, uint64_t v) {
    asm("mov.b64 {%0, %1}, %2;" : "=f"(lo), "=f"(hi) : "l"(v));
}

// projected q: [bh][seq][32] ; projected k TRANSPOSED: [bh][d][seq]
__device__ float g_q [(size_t)BHN * Q_LEN * HD];
__device__ float g_kt[(size_t)BHN * HD * K_LEN];
__device__ float g_pe[(size_t)Q_LEN * EMB];

// ───────────────────────── PE table ─────────────────────────
__global__ void pe_kernel() {
    int idx = blockIdx.x * 256 + threadIdx.x;
    int pos = idx >> 8;
    int i2  = idx & 255;
    float e = 2.0f * (float)i2;
    float div = expf(e * (-9.210340371976184f / 512.0f));
    float a = (float)pos * div;
    g_pe[(size_t)pos * EMB + 2 * i2]     = sinf(a);
    g_pe[(size_t)pos * EMB + 2 * i2 + 1] = cosf(a);
}

// ───────────────────────── projection (FFMA2) ─────────────────────────
__global__ void __launch_bounds__(256, 2) proj_kernel(
        const float* __restrict__ qin, const float* __restrict__ kin,
        const float* __restrict__ Wq,  const float* __restrict__ bq,
        const float* __restrict__ Wk,  const float* __restrict__ bk) {
    __shared__ float sh[32 * 36 + 32 * 256];   // As | Bs ; reused as transpose buf
    float* As = sh;             // [r][e] stride 36 (rows 16B-aligned: 144B)
    float* Bs = sh + 32 * 36;   // [e][col]

    const int is_q = (blockIdx.z == 0);
    const float* in   = is_q ? qin : kin;
    const float* W    = is_q ? Wq  : Wk;
    const float* bias = is_q ? bq  : bk;
    const int off     = is_q ? 0 : 256;

    int b  = blockIdx.y;
    int q0 = blockIdx.x * 32;
    int col = threadIdx.x;

    // acc2[r] = (even-e partial, odd-e partial); bias seeded into .lo
    uint64_t acc2[32];
    {
        float bv = bias[off + col];
        uint64_t init = pack2(bv, 0.f);
#pragma unroll
        for (int r = 0; r < 32; r++) acc2[r] = init;
    }

    for (int et = 0; et < 16; et++) {
        {
            int i = threadIdx.x;
#pragma unroll
            for (int j = 0; j < 4; j++, i += 256) {
                int r = i >> 5, e = i & 31;
                int ge = et * 32 + e;
                float v = in[((size_t)(q0 + r) * BATCH + b) * EMB + ge];
                if (is_q) v += g_pe[(size_t)(q0 + r) * EMB + ge];
                As[r * 36 + e] = v;
            }
        }
#pragma unroll
        for (int e = 0; e < 32; e++)
            Bs[e * 256 + col] = W[(size_t)(et * 32 + e) * INP + off + col];
        __syncthreads();

#pragma unroll
        for (int e4 = 0; e4 < 8; e4++) {
            uint64_t b01 = pack2(Bs[(e4 * 4 + 0) * 256 + col],
                                 Bs[(e4 * 4 + 1) * 256 + col]);
            uint64_t b23 = pack2(Bs[(e4 * 4 + 2) * 256 + col],
                                 Bs[(e4 * 4 + 3) * 256 + col]);
#pragma unroll
            for (int r = 0; r < 32; r++) {
                ulonglong2 a2 = *(const ulonglong2*)&As[r * 36 + e4 * 4];
                FMA2(acc2[r], a2.x, b01);
                FMA2(acc2[r], a2.y, b23);
            }
        }
        __syncthreads();
    }

    float acc[32];
#pragma unroll
    for (int r = 0; r < 32; r++) {
        float lo, hi;
        unpack2(lo, hi, acc2[r]);
        acc[r] = lo + hi;
    }

    if (is_q) {
        int h = col >> 5, d = col & 31;
#pragma unroll
        for (int r = 0; r < 32; r++)
            g_q[((size_t)(b * HEADS + h) * Q_LEN + (q0 + r)) * HD + d] = acc[r];
    } else {
        // transpose through smem: T[r][col], stride 257 (conflict-free read)
        float* T = sh;
#pragma unroll
        for (int r = 0; r < 32; r++) T[r * 257 + col] = acc[r];
        __syncthreads();
#pragma unroll
        for (int j = 0; j < 32; j++) {
            int i = threadIdx.x + j * 256;
            int r = i & 31, c = i >> 5;          // lane == r -> coalesced store
            int h = c >> 5, d = c & 31;
            g_kt[(((size_t)(b * HEADS + h)) * HD + d) * K_LEN + q0 + r] = T[r * 257 + c];
        }
    }
}

// ───────────────────────── attention (FFMA2) ─────────────────────────
// Block: 16 q-rows x full K=2048 for one (b,h). 512 threads, thread owns
// k = 4*tid..4*tid+3 (two f32x2 column pairs). k streams L2->regs as
// ulonglong2 LDG.128 from g_kt; q broadcast from smem strip + splat packs.
__global__ void __launch_bounds__(512, 1) attn_kernel(
        const unsigned char* __restrict__ attn_mask,
        const unsigned char* __restrict__ kpm,
        float* __restrict__ out) {
    __shared__ float qs[16 * 32];
    __shared__ float red[16 * 16];
    __shared__ float rinv[16];

    int bh = blockIdx.y;               // b*8 + h
    int b = bh >> 3, h = bh & 7;
    int q0 = blockIdx.x * 16;
    int tid = threadIdx.x, w = tid >> 5, lane = tid & 31;

    qs[tid] = g_q[((size_t)bh * Q_LEN + q0) * HD + tid];
    __syncthreads();

    // acc2[r][cp]: .lo = col 4*tid+2cp, .hi = col 4*tid+2cp+1 (full sums)
    uint64_t acc2[16][2];
    uint64_t z = pack2(0.f, 0.f);
#pragma unroll
    for (int r = 0; r < 16; r++) { acc2[r][0] = z; acc2[r][1] = z; }

    const float* kbase = g_kt + (size_t)bh * HD * K_LEN + 4 * tid;

#pragma unroll
    for (int dc = 0; dc < 8; dc++) {
        ulonglong2 kk[4];
#pragma unroll
        for (int j = 0; j < 4; j++)
            kk[j] = *(const ulonglong2*)(kbase + (size_t)(dc * 4 + j) * K_LEN);
#pragma unroll
        for (int r = 0; r < 16; r++) {
            float4 q4 = *(const float4*)&qs[r * 32 + dc * 4];   // uniform broadcast
            uint64_t qx = pack2(q4.x, q4.x);
            FMA2(acc2[r][0], qx, kk[0].x);
            FMA2(acc2[r][1], qx, kk[0].y);
            uint64_t qy = pack2(q4.y, q4.y);
            FMA2(acc2[r][0], qy, kk[1].x);
            FMA2(acc2[r][1], qy, kk[1].y);
            uint64_t qz = pack2(q4.z, q4.z);
            FMA2(acc2[r][0], qz, kk[2].x);
            FMA2(acc2[r][1], qz, kk[2].y);
            uint64_t qw = pack2(q4.w, q4.w);
            FMA2(acc2[r][0], qw, kk[3].x);
            FMA2(acc2[r][1], qw, kk[3].y);
        }
    }

    // masks (vectorized uchar4; k = 4*tid + {0..3})
    uchar4 pm4 = ((const uchar4*)(kpm + (size_t)b * K_LEN))[tid];
    float acc[16][4];
#pragma unroll
    for (int r = 0; r < 16; r++) {
        unpack2(acc[r][0], acc[r][1], acc2[r][0]);
        unpack2(acc[r][2], acc[r][3], acc2[r][1]);
        uchar4 m4 = ((const uchar4*)(attn_mask + (size_t)(q0 + r) * K_LEN))[tid];
        if (pm4.x | m4.x) acc[r][0] = -1000.f;
        if (pm4.y | m4.y) acc[r][1] = -1000.f;
        if (pm4.z | m4.z) acc[r][2] = -1000.f;
        if (pm4.w | m4.w) acc[r][3] = -1000.f;
    }

    // softmax without max-subtraction (scores O(±8); exp(-1000) underflows to 0
    // exactly as the fp32 reference does)
#pragma unroll
    for (int r = 0; r < 16; r++) {
        float p0 = __expf(acc[r][0]);
        float p1 = __expf(acc[r][1]);
        float p2 = __expf(acc[r][2]);
        float p3 = __expf(acc[r][3]);
        acc[r][0] = p0; acc[r][1] = p1; acc[r][2] = p2; acc[r][3] = p3;
        float s = (p0 + p1) + (p2 + p3);
#pragma unroll
        for (int o = 16; o > 0; o >>= 1) s += __shfl_xor_sync(0xffffffffu, s, o);
        if (lane == 0) red[r * 16 + w] = s;
    }
    __syncthreads();
    {
        float v = (lane < 16) ? red[w * 16 + lane] : 0.f;
#pragma unroll
        for (int o = 8; o > 0; o >>= 1) v += __shfl_xor_sync(0xffffffffu, v, o);
        if (lane == 0) rinv[w] = 1.0f / v;
    }
    __syncthreads();

#pragma unroll
    for (int r = 0; r < 16; r++) {
        float iv = rinv[r];
        float4 o4 = make_float4(acc[r][0] * iv, acc[r][1] * iv,
                                acc[r][2] * iv, acc[r][3] * iv);
        *(float4*)&out[(((size_t)(h * BATCH + b)) * Q_LEN + q0 + r) * K_LEN + 4 * tid] = o4;
    }
}

extern "C" void kernel_launch(void* const* d_in, const int* in_sizes, int n_in,
                              void* d_out, int out_size) {
    const float* query = (const float*)d_in[0];
    const float* key   = (const float*)d_in[1];
    const float* Wq    = (const float*)d_in[2];
    const float* bq    = (const float*)d_in[3];
    const float* Wk    = (const float*)d_in[4];
    const float* bk    = (const float*)d_in[5];
    const unsigned char* kpm = (const unsigned char*)d_in[6];
    const unsigned char* am  = (const unsigned char*)d_in[7];
    float* out = (float*)d_out;

    pe_kernel<<<2048, 256>>>();
    proj_kernel<<<dim3(Q_LEN / 32, BATCH, 2), 256>>>(query, key, Wq, bq, Wk, bk);
    attn_kernel<<<dim3(Q_LEN / 16, BHN), 512>>>(am, kpm, out);
}

// round 8
// speedup vs baseline: 1.1658x; 1.0312x over previous
#include <cuda_runtime.h>
#include <math.h>
#include <stdint.h>

#define Q_LEN 2048
#define K_LEN 2048
#define BATCH 4
#define HEADS 8
#define EMB 512
#define INP 544
#define HD 32
#define BHN (BATCH*HEADS)

// projected q: [bh][seq][32] ; projected k TRANSPOSED: [bh][d][seq]
__device__ float g_q [(size_t)BHN * Q_LEN * HD];
__device__ float g_kt[(size_t)BHN * HD * K_LEN];
__device__ float g_pe[(size_t)Q_LEN * EMB];
__device__ int g_dummy;

// ─────────────────── profiler-alignment dummy (launch #0) ───────────────────
__global__ void warm_kernel() { g_dummy = 1; }

// ───────────────────────── PE table ─────────────────────────
__global__ void pe_kernel() {
    int idx = blockIdx.x * 256 + threadIdx.x;
    int pos = idx >> 8;
    int i2  = idx & 255;
    float e = 2.0f * (float)i2;
    float div = expf(e * (-9.210340371976184f / 512.0f));
    float a = (float)pos * div;
    g_pe[(size_t)pos * EMB + 2 * i2]     = sinf(a);
    g_pe[(size_t)pos * EMB + 2 * i2 + 1] = cosf(a);
}

// ───────────────────────── projection ─────────────────────────
__global__ void __launch_bounds__(256, 2) proj_kernel(
        const float* __restrict__ qin, const float* __restrict__ kin,
        const float* __restrict__ Wq,  const float* __restrict__ bq,
        const float* __restrict__ Wk,  const float* __restrict__ bk) {
    __shared__ float sh[32 * 36 + 32 * 256];   // As | Bs ; reused as transpose buf
    float* As = sh;             // [r][e] stride 36
    float* Bs = sh + 32 * 36;   // [e][col]

    const int is_q = (blockIdx.z == 0);
    const float* in   = is_q ? qin : kin;
    const float* W    = is_q ? Wq  : Wk;
    const float* bias = is_q ? bq  : bk;
    const int off     = is_q ? 0 : 256;

    int b  = blockIdx.y;
    int q0 = blockIdx.x * 32;
    int col = threadIdx.x;

    float acc[32];
    float bv = bias[off + col];
#pragma unroll
    for (int r = 0; r < 32; r++) acc[r] = bv;

    for (int et = 0; et < 16; et++) {
        {
            int i = threadIdx.x;
#pragma unroll
            for (int j = 0; j < 4; j++, i += 256) {
                int r = i >> 5, e = i & 31;
                int ge = et * 32 + e;
                float v = in[((size_t)(q0 + r) * BATCH + b) * EMB + ge];
                if (is_q) v += g_pe[(size_t)(q0 + r) * EMB + ge];
                As[r * 36 + e] = v;
            }
        }
#pragma unroll
        for (int e = 0; e < 32; e++)
            Bs[e * 256 + col] = W[(size_t)(et * 32 + e) * INP + off + col];
        __syncthreads();

#pragma unroll
        for (int e4 = 0; e4 < 8; e4++) {
            float b0 = Bs[(e4 * 4 + 0) * 256 + col];
            float b1 = Bs[(e4 * 4 + 1) * 256 + col];
            float b2 = Bs[(e4 * 4 + 2) * 256 + col];
            float b3 = Bs[(e4 * 4 + 3) * 256 + col];
#pragma unroll
            for (int r = 0; r < 32; r++) {
                float4 a4 = *(const float4*)&As[r * 36 + e4 * 4];
                acc[r] += a4.x * b0;
                acc[r] += a4.y * b1;
                acc[r] += a4.z * b2;
                acc[r] += a4.w * b3;
            }
        }
        __syncthreads();
    }

    if (is_q) {
        int h = col >> 5, d = col & 31;
#pragma unroll
        for (int r = 0; r < 32; r++)
            g_q[((size_t)(b * HEADS + h) * Q_LEN + (q0 + r)) * HD + d] = acc[r];
    } else {
        // transpose through smem: T[r][col], stride 257 (conflict-free read)
        float* T = sh;
#pragma unroll
        for (int r = 0; r < 32; r++) T[r * 257 + col] = acc[r];
        __syncthreads();
#pragma unroll
        for (int j = 0; j < 32; j++) {
            int i = threadIdx.x + j * 256;
            int r = i & 31, c = i >> 5;          // lane == r -> coalesced store
            int h = c >> 5, d = c & 31;
            g_kt[(((size_t)(b * HEADS + h)) * HD + d) * K_LEN + q0 + r] = T[r * 257 + c];
        }
    }
}

// ───────────────────────── attention ─────────────────────────
// Block: 16 q-rows x full K=2048 for one (b,h). 512 threads, thread owns
// k = 4*tid..4*tid+3. k streams L2->registers (coalesced LDG.128 from g_kt,
// double-buffered across dc iterations); q broadcast from a 2KB smem strip.
__global__ void __launch_bounds__(512, 1) attn_kernel(
        const unsigned char* __restrict__ attn_mask,
        const unsigned char* __restrict__ kpm,
        float* __restrict__ out) {
    __shared__ float qs[16 * 32];
    __shared__ float red[16 * 16];
    __shared__ float rinv[16];

    int bh = blockIdx.y;               // b*8 + h
    int b = bh >> 3, h = bh & 7;
    int q0 = blockIdx.x * 16;
    int tid = threadIdx.x, w = tid >> 5, lane = tid & 31;

    qs[tid] = g_q[((size_t)bh * Q_LEN + q0) * HD + tid];
    __syncthreads();

    float acc[16][4];
#pragma unroll
    for (int r = 0; r < 16; r++)
#pragma unroll
        for (int j = 0; j < 4; j++) acc[r][j] = 0.f;

    const float* kbase = g_kt + (size_t)bh * HD * K_LEN + 4 * tid;

    // k double buffer (prefetch dc+1 while computing dc)
    float4 cur[4], nxt[4];
#pragma unroll
    for (int j = 0; j < 4; j++)
        cur[j] = __ldg((const float4*)(kbase + (size_t)j * K_LEN));

#pragma unroll
    for (int dc = 0; dc < 8; dc++) {
        if (dc < 7) {
#pragma unroll
            for (int j = 0; j < 4; j++)
                nxt[j] = __ldg((const float4*)(kbase + (size_t)((dc + 1) * 4 + j) * K_LEN));
        }
#pragma unroll
        for (int r = 0; r < 16; r++) {
            float4 q4 = *(const float4*)&qs[r * 32 + dc * 4];   // uniform broadcast
            acc[r][0] += q4.x * cur[0].x; acc[r][1] += q4.x * cur[0].y;
            acc[r][2] += q4.x * cur[0].z; acc[r][3] += q4.x * cur[0].w;
            acc[r][0] += q4.y * cur[1].x; acc[r][1] += q4.y * cur[1].y;
            acc[r][2] += q4.y * cur[1].z; acc[r][3] += q4.y * cur[1].w;
            acc[r][0] += q4.z * cur[2].x; acc[r][1] += q4.z * cur[2].y;
            acc[r][2] += q4.z * cur[2].z; acc[r][3] += q4.z * cur[2].w;
            acc[r][0] += q4.w * cur[3].x; acc[r][1] += q4.w * cur[3].y;
            acc[r][2] += q4.w * cur[3].z; acc[r][3] += q4.w * cur[3].w;
        }
#pragma unroll
        for (int j = 0; j < 4; j++) cur[j] = nxt[j];
    }

    // masks (vectorized uchar4; k = 4*tid + {0..3})
    uchar4 pm4 = ((const uchar4*)(kpm + (size_t)b * K_LEN))[tid];
#pragma unroll
    for (int r = 0; r < 16; r++) {
        uchar4 m4 = ((const uchar4*)(attn_mask + (size_t)(q0 + r) * K_LEN))[tid];
        if (pm4.x | m4.x) acc[r][0] = -1000.f;
        if (pm4.y | m4.y) acc[r][1] = -1000.f;
        if (pm4.z | m4.z) acc[r][2] = -1000.f;
        if (pm4.w | m4.w) acc[r][3] = -1000.f;
    }

    // softmax without max-subtraction (scores O(±8); exp(-1000) underflows to 0
    // exactly as the fp32 reference does)
#pragma unroll
    for (int r = 0; r < 16; r++) {
        float p0 = __expf(acc[r][0]);
        float p1 = __expf(acc[r][1]);
        float p2 = __expf(acc[r][2]);
        float p3 = __expf(acc[r][3]);
        acc[r][0] = p0; acc[r][1] = p1; acc[r][2] = p2; acc[r][3] = p3;
        float s = (p0 + p1) + (p2 + p3);
#pragma unroll
        for (int o = 16; o > 0; o >>= 1) s += __shfl_xor_sync(0xffffffffu, s, o);
        if (lane == 0) red[r * 16 + w] = s;
    }
    __syncthreads();
    {
        float v = (lane < 16) ? red[w * 16 + lane] : 0.f;
#pragma unroll
        for (int o = 8; o > 0; o >>= 1) v += __shfl_xor_sync(0xffffffffu, v, o);
        if (lane == 0) rinv[w] = 1.0f / v;
    }
    __syncthreads();

#pragma unroll
    for (int r = 0; r < 16; r++) {
        float iv = rinv[r];
        float4 o4 = make_float4(acc[r][0] * iv, acc[r][1] * iv,
                                acc[r][2] * iv, acc[r][3] * iv);
        *(float4*)&out[(((size_t)(h * BATCH + b)) * Q_LEN + q0 + r) * K_LEN + 4 * tid] = o4;
    }
}

extern "C" void kernel_launch(void* const* d_in, const int* in_sizes, int n_in,
                              void* d_out, int out_size) {
    const float* query = (const float*)d_in[0];
    const float* key   = (const float*)d_in[1];
    const float* Wq    = (const float*)d_in[2];
    const float* bq    = (const float*)d_in[3];
    const float* Wk    = (const float*)d_in[4];
    const float* bk    = (const float*)d_in[5];
    const unsigned char* kpm = (const unsigned char*)d_in[6];
    const unsigned char* am  = (const unsigned char*)d_in[7];
    float* out = (float*)d_out;

    warm_kernel<<<1, 1>>>();   // aligns ncu capture (4th launch) onto attn_kernel
    pe_kernel<<<2048, 256>>>();
    proj_kernel<<<dim3(Q_LEN / 32, BATCH, 2), 256>>>(query, key, Wq, bq, Wk, bk);
    attn_kernel<<<dim3(Q_LEN / 16, BHN), 512>>>(am, kpm, out);
}